// round 8
// baseline (speedup 1.0000x reference)
#include <cuda_runtime.h>

// Problem constants (fixed for this registry problem instance)
#define BB 32
#define ZZ 384
#define NV 68
#define MC 46
#define DC 7
#define EE (MC*DC)          // 322
#define GB 4                // batch elements per phase1 block

// Device scratch (no cudaMalloc allowed)
__device__ float g_tot[BB*NV*ZZ];     // tot_plus = xa + sum(c2v), layout [b][n][z]
__device__ float g_xaT[BB*NV*ZZ];     // transposed xa, layout [b][n][z]
// c2v stored in VARIABLE z-domain: c2v_v[b][e][zv], zv=(zm+shift_e)%Z.
// Phase2 reads/writes at the rotated index zv (same index as its tot read);
// phase1 reads it un-rotated and fully vectorized.
__device__ float g_c2v[BB*EE*ZZ];
__device__ int   g_inv_off[NV+1];     // CSR: variable -> its edges
__device__ int   g_inv_eoff[EE];      // per edge (var-sorted): e*ZZ

// ---------------------------------------------------------------------------
// Init: tiled transpose xa[b][z][n] -> g_xaT/g_tot [b][n][z].
// Both gmem sides coalesced via a 32x33 smem tile.
// grid.x = BB * (ZZ/32) * 3 n-tiles, block (32,8).
// ---------------------------------------------------------------------------
__global__ void k_init(const float* __restrict__ xa) {
    __shared__ float tile[32][33];
    int bid = blockIdx.x;
    int nt = bid % 3;                 // n-tile (0..2, covers 96 >= 68)
    int zt = (bid / 3) % (ZZ/32);     // z-tile
    int b  = bid / (3 * (ZZ/32));
    int n0 = nt * 32, z0 = zt * 32;
    int tx = threadIdx.x, ty = threadIdx.y;

    int n = n0 + tx;
#pragma unroll
    for (int r = 0; r < 4; r++) {
        int z = z0 + ty + r*8;
        if (n < NV) tile[ty + r*8][tx] = xa[(b*ZZ + z)*NV + n];
    }
    __syncthreads();
#pragma unroll
    for (int r = 0; r < 4; r++) {
        int nn = n0 + ty + r*8;
        int zz = z0 + tx;
        if (nn < NV) {
            float v = tile[tx][ty + r*8];
            int idx = (b*NV + nn)*ZZ + zz;
            g_xaT[idx] = v;
            g_tot[idx] = v;          // iteration 0: c2v = 0 -> tot_plus = xa
        }
    }
}

// ---------------------------------------------------------------------------
// Build inverse index: variable n -> list of e*ZZ.
// (Order irrelevant: half-integer sums are exact in fp32 in any order.)
// ---------------------------------------------------------------------------
__global__ void k_build_inv(const int* __restrict__ vn) {
    __shared__ int off[NV+1];
    __shared__ int cur[NV];
    int t = threadIdx.x;
    for (int i = t; i <= NV; i += blockDim.x) off[i] = 0;
    __syncthreads();
    for (int e = t; e < EE; e += blockDim.x) atomicAdd(&off[vn[e] + 1], 1);
    __syncthreads();
    if (t == 0) {
        int s = 0;
        for (int i = 0; i <= NV; i++) { s += off[i]; off[i] = s; }
    }
    __syncthreads();
    for (int i = t; i <= NV; i += blockDim.x) g_inv_off[i] = off[i];
    for (int i = t; i <  NV; i += blockDim.x) cur[i] = off[i];
    __syncthreads();
    for (int e = t; e < EE; e += blockDim.x) {
        int p = atomicAdd(&cur[vn[e]], 1);
        g_inv_eoff[p] = e * ZZ;
    }
}

// ---------------------------------------------------------------------------
// Phase 2: check-node min-sum. One block per (b, check c), 384 threads = zm.
// Edge j uses rotated index zv_j=(zm+shift_j)%Z for tot read, old-c2v read,
// and new-c2v write (c2v lives in variable domain). All coalesced.
// ---------------------------------------------------------------------------
__global__ void __launch_bounds__(ZZ) k_phase2(
    const int* __restrict__ vn, const int* __restrict__ sh,
    const float* __restrict__ cw, int it, int first) {
    int c = blockIdx.x % MC;
    int b = blockIdx.x / MC;
    int zm = threadIdx.x;

    __shared__ int s_n[DC], s_s[DC];
    if (threadIdx.x < DC) {
        int e = c * DC + threadIdx.x;
        s_n[threadIdx.x] = vn[e];
        s_s[threadIdx.x] = sh[e];
    }
    __syncthreads();

    const float* totb = g_tot + b*NV*ZZ;
    float*       cvb  = g_c2v + (b*EE + c*DC)*ZZ;   // edge j row: + j*ZZ
    float w = __ldg(cw + it);

    int zv[DC];
#pragma unroll
    for (int j = 0; j < DC; j++) {
        int t2 = zm + s_s[j]; if (t2 >= ZZ) t2 -= ZZ;
        zv[j] = t2;
    }

    // gather tot + old c2v (independent loads -> MLP)
    float tp[DC], old[DC];
#pragma unroll
    for (int j = 0; j < DC; j++) tp[j]  = totb[s_n[j]*ZZ + zv[j]];
#pragma unroll
    for (int j = 0; j < DC; j++) old[j] = first ? 0.0f : cvb[j*ZZ + zv[j]];

    float mn1 = 1e30f, mn2 = 1e30f;
    int arg = 0;
    unsigned sb = 0;
#pragma unroll
    for (int j = 0; j < DC; j++) {
        float x = tp[j] - old[j];
        x = fminf(fmaxf(x, -20.0f), 20.0f);
        if (x < 0.0f) sb |= (1u << j);
        float a = fabsf(x);
        if (a < mn1) { mn2 = mn1; mn1 = a; arg = j; }
        else         { mn2 = fminf(mn2, a); }
    }
    int par = __popc(sb) & 1;
    // quantize: clip(round(2*w*min)/2, +-7.5); rintf = round-half-even = jnp.round
    float mag1 = 0.5f * fminf(fmaxf(rintf(2.0f * (w * mn1)), -15.0f), 15.0f);
    float mag2 = 0.5f * fminf(fmaxf(rintf(2.0f * (w * mn2)), -15.0f), 15.0f);

#pragma unroll
    for (int j = 0; j < DC; j++) {
        float m = (j == arg) ? mag2 : mag1;               // branch-free SEL
        unsigned neg = (unsigned)((par ^ (int)(sb >> j)) & 1) << 31;  // extrinsic sign
        cvb[j*ZZ + zv[j]] = __uint_as_float(__float_as_uint(m) ^ neg);
    }
}

// ---------------------------------------------------------------------------
// Phase 1: variable-node sum, vectorized + batch-grouped for MLP.
// One block per (n, group of GB batch elements), 96 threads = float4 over z.
// Each thread runs GB independent accumulation chains -> GB independent
// LDG.128 per edge step (x2 with unroll) instead of 1: hides L2/DRAM latency.
// Edge rows are read at plain offset z (c2v in variable domain, 16B aligned).
// Sum of half-integer c2v exact in any order; tot = xa + s one rounded add:
// bit-exact vs JAX. dst==nullptr -> g_tot; else final output (same layout).
// ---------------------------------------------------------------------------
__global__ void __launch_bounds__(ZZ/4) k_phase1(float* __restrict__ dst) {
    int n  = blockIdx.x % NV;
    int b0 = (blockIdx.x / NV) * GB;
    int z4 = threadIdx.x * 4;

    __shared__ int s_eo[32];                 // deg << 32 always
    int k0 = g_inv_off[n], k1 = g_inv_off[n+1];
    int deg = k1 - k0;
    if (threadIdx.x < deg) s_eo[threadIdx.x] = g_inv_eoff[k0 + threadIdx.x];
    __syncthreads();

    const float* cv0 = g_c2v + b0*EE*ZZ + z4;
    float4 acc[GB];
#pragma unroll
    for (int g = 0; g < GB; g++) acc[g] = make_float4(0.f, 0.f, 0.f, 0.f);

#pragma unroll 2
    for (int k = 0; k < deg; k++) {
        int eo = s_eo[k];
        float4 v[GB];
#pragma unroll
        for (int g = 0; g < GB; g++)
            v[g] = *(const float4*)(cv0 + g*(EE*ZZ) + eo);
#pragma unroll
        for (int g = 0; g < GB; g++) {
            acc[g].x += v[g].x; acc[g].y += v[g].y;
            acc[g].z += v[g].z; acc[g].w += v[g].w;
        }
    }

    float* outp = dst ? dst : g_tot;
#pragma unroll
    for (int g = 0; g < GB; g++) {
        int idx = ((b0 + g)*NV + n)*ZZ + z4;
        float4 xa4 = *(const float4*)(g_xaT + idx);
        float4 o = make_float4(xa4.x + acc[g].x, xa4.y + acc[g].y,
                               xa4.z + acc[g].z, xa4.w + acc[g].w);
        *(float4*)(outp + idx) = o;          // out[b, n*Z + z] == [b][n][z]
    }
}

// ---------------------------------------------------------------------------
extern "C" void kernel_launch(void* const* d_in, const int* in_sizes, int n_in,
                              void* d_out, int out_size) {
    const float* xa = (const float*)d_in[0];
    const float* cw = (const float*)d_in[1];
    const int*   vn = (const int*)d_in[2];
    // d_in[3] = cn_idx: structure is repeat(arange(M), dc) -> implicit (e/7)
    const int*   sh = (const int*)d_in[4];

    int iters = in_sizes[1];   // cn_weights length = 8

    k_init<<<BB * (ZZ/32) * 3, dim3(32, 8)>>>(xa);
    k_build_inv<<<1, 256>>>(vn);

    for (int it = 0; it < iters; ++it) {
        k_phase2<<<BB*MC, ZZ>>>(vn, sh, cw, it, it == 0);
        k_phase1<<<NV * (BB/GB), ZZ/4>>>((it == iters-1) ? (float*)d_out : (float*)nullptr);
    }
}

// round 9
// speedup vs baseline: 1.1843x; 1.1843x over previous
#include <cuda_runtime.h>

// Problem constants (fixed for this registry problem instance)
#define BB 32
#define ZZ 384
#define NV 68
#define MC 46
#define DC 7
#define EE (MC*DC)          // 322
#define NG 4                // variables per phase1 block (68 = 17*4)

// Device scratch (no cudaMalloc allowed)
__device__ float g_tot[BB*NV*ZZ];     // tot_plus = xa + sum(c2v), layout [b][n][z]
__device__ float g_xaT[BB*NV*ZZ];     // transposed xa, layout [b][n][z]
// c2v stored in VARIABLE z-domain: c2v_v[b][e][zv], zv=(zm+shift_e)%Z.
// Phase2 reads/writes at the rotated index zv (same index as its tot read);
// phase1 reads it un-rotated and fully vectorized.
__device__ float g_c2v[BB*EE*ZZ];
__device__ int   g_inv_off[NV+1];     // CSR: variable -> its edges
__device__ int   g_inv_eoff[EE];      // per edge (var-sorted): e*ZZ

// ---------------------------------------------------------------------------
// Init: tiled transpose xa[b][z][n] -> g_xaT/g_tot [b][n][z].
// Both gmem sides coalesced via a 32x33 smem tile.
// ---------------------------------------------------------------------------
__global__ void k_init(const float* __restrict__ xa) {
    __shared__ float tile[32][33];
    int bid = blockIdx.x;
    int nt = bid % 3;                 // n-tile (0..2, covers 96 >= 68)
    int zt = (bid / 3) % (ZZ/32);     // z-tile
    int b  = bid / (3 * (ZZ/32));
    int n0 = nt * 32, z0 = zt * 32;
    int tx = threadIdx.x, ty = threadIdx.y;

    int n = n0 + tx;
#pragma unroll
    for (int r = 0; r < 4; r++) {
        int z = z0 + ty + r*8;
        if (n < NV) tile[ty + r*8][tx] = xa[(b*ZZ + z)*NV + n];
    }
    __syncthreads();
#pragma unroll
    for (int r = 0; r < 4; r++) {
        int nn = n0 + ty + r*8;
        int zz = z0 + tx;
        if (nn < NV) {
            float v = tile[tx][ty + r*8];
            int idx = (b*NV + nn)*ZZ + zz;
            g_xaT[idx] = v;
            g_tot[idx] = v;          // iteration 0: c2v = 0 -> tot_plus = xa
        }
    }
}

// ---------------------------------------------------------------------------
// Build inverse index: variable n -> list of e*ZZ.
// (Order irrelevant: half-integer sums are exact in fp32 in any order.)
// ---------------------------------------------------------------------------
__global__ void k_build_inv(const int* __restrict__ vn) {
    __shared__ int off[NV+1];
    __shared__ int cur[NV];
    int t = threadIdx.x;
    for (int i = t; i <= NV; i += blockDim.x) off[i] = 0;
    __syncthreads();
    for (int e = t; e < EE; e += blockDim.x) atomicAdd(&off[vn[e] + 1], 1);
    __syncthreads();
    if (t == 0) {
        int s = 0;
        for (int i = 0; i <= NV; i++) { s += off[i]; off[i] = s; }
    }
    __syncthreads();
    for (int i = t; i <= NV; i += blockDim.x) g_inv_off[i] = off[i];
    for (int i = t; i <  NV; i += blockDim.x) cur[i] = off[i];
    __syncthreads();
    for (int e = t; e < EE; e += blockDim.x) {
        int p = atomicAdd(&cur[vn[e]], 1);
        g_inv_eoff[p] = e * ZZ;
    }
}

// ---------------------------------------------------------------------------
// Phase 2: check-node min-sum. One block per (b, check c), 384 threads = zm.
// Edge j uses rotated index zv_j=(zm+shift_j)%Z for tot read, old-c2v read,
// and new-c2v write (c2v lives in variable domain). All coalesced.
// ---------------------------------------------------------------------------
__global__ void __launch_bounds__(ZZ) k_phase2(
    const int* __restrict__ vn, const int* __restrict__ sh,
    const float* __restrict__ cw, int it, int first) {
    int c = blockIdx.x % MC;
    int b = blockIdx.x / MC;
    int zm = threadIdx.x;

    __shared__ int s_n[DC], s_s[DC];
    if (threadIdx.x < DC) {
        int e = c * DC + threadIdx.x;
        s_n[threadIdx.x] = vn[e];
        s_s[threadIdx.x] = sh[e];
    }
    __syncthreads();

    const float* totb = g_tot + b*NV*ZZ;
    float*       cvb  = g_c2v + (b*EE + c*DC)*ZZ;   // edge j row: + j*ZZ
    float w = __ldg(cw + it);

    int zv[DC];
#pragma unroll
    for (int j = 0; j < DC; j++) {
        int t2 = zm + s_s[j]; if (t2 >= ZZ) t2 -= ZZ;
        zv[j] = t2;
    }

    // gather tot + old c2v (independent loads -> MLP)
    float tp[DC], old[DC];
#pragma unroll
    for (int j = 0; j < DC; j++) tp[j]  = totb[s_n[j]*ZZ + zv[j]];
#pragma unroll
    for (int j = 0; j < DC; j++) old[j] = first ? 0.0f : cvb[j*ZZ + zv[j]];

    float mn1 = 1e30f, mn2 = 1e30f;
    int arg = 0;
    unsigned sb = 0;
#pragma unroll
    for (int j = 0; j < DC; j++) {
        float x = tp[j] - old[j];
        x = fminf(fmaxf(x, -20.0f), 20.0f);
        if (x < 0.0f) sb |= (1u << j);
        float a = fabsf(x);
        if (a < mn1) { mn2 = mn1; mn1 = a; arg = j; }
        else         { mn2 = fminf(mn2, a); }
    }
    int par = __popc(sb) & 1;
    // quantize: clip(round(2*w*min)/2, +-7.5); rintf = round-half-even = jnp.round
    float mag1 = 0.5f * fminf(fmaxf(rintf(2.0f * (w * mn1)), -15.0f), 15.0f);
    float mag2 = 0.5f * fminf(fmaxf(rintf(2.0f * (w * mn2)), -15.0f), 15.0f);

#pragma unroll
    for (int j = 0; j < DC; j++) {
        float m = (j == arg) ? mag2 : mag1;               // branch-free SEL
        unsigned neg = (unsigned)((par ^ (int)(sb >> j)) & 1) << 31;  // extrinsic sign
        cvb[j*ZZ + zv[j]] = __uint_as_float(__float_as_uint(m) ^ neg);
    }
}

// ---------------------------------------------------------------------------
// Phase 1: variable-node sum, vectorized, phase2-shaped blocks.
// One block per (b, group of NG=4 variables), 384 threads.
// Thread -> nn = tid/96 (warp-uniform: 96 = 3 warps), z4 = (tid%96)*4.
// One accumulation chain per thread (max TLP, the R8 lesson), float4 loads
// at plain offset z (c2v in variable domain, 16B aligned), __ldg non-coherent.
// Sum of half-integer c2v exact in any order; tot = xa + s one rounded add:
// bit-exact vs JAX. dst==nullptr -> g_tot; else final output (same layout).
// ---------------------------------------------------------------------------
__global__ void __launch_bounds__(ZZ) k_phase1(float* __restrict__ dst) {
    int n0 = (blockIdx.x % (NV/NG)) * NG;
    int b  = blockIdx.x / (NV/NG);
    int nn = threadIdx.x / (ZZ/4);           // 0..3, uniform per warp
    int z4 = (threadIdx.x % (ZZ/4)) * 4;
    int n  = n0 + nn;

    __shared__ int s_eo[NG][16];             // deg << 16 always
    __shared__ int s_k0[NG+1];
    if (threadIdx.x <= NG) s_k0[threadIdx.x] = g_inv_off[n0 + threadIdx.x];
    __syncthreads();
    int base = s_k0[0];
    int tot_e = s_k0[NG] - base;
    if (threadIdx.x < tot_e) {
        int eo = g_inv_eoff[base + threadIdx.x];
        // scatter into per-n table
        int i = threadIdx.x + base;
        int g = 0;
        while (i >= s_k0[g+1]) g++;          // tiny loop, <=4 iters, few threads
        s_eo[g][i - s_k0[g]] = eo;
    }
    __syncthreads();

    int deg = s_k0[nn+1] - s_k0[nn];
    const float* cvb = g_c2v + b*EE*ZZ + z4;
    float4 s = make_float4(0.f, 0.f, 0.f, 0.f);
    for (int k = 0; k < deg; k++) {
        float4 v = __ldg((const float4*)(cvb + s_eo[nn][k]));
        s.x += v.x; s.y += v.y; s.z += v.z; s.w += v.w;
    }
    int idx = (b*NV + n)*ZZ + z4;
    float4 xa4 = __ldg((const float4*)(g_xaT + idx));
    float4 o = make_float4(xa4.x + s.x, xa4.y + s.y, xa4.z + s.z, xa4.w + s.w);
    if (dst) *(float4*)(dst + idx)   = o;    // out[b, n*Z + z] == [b][n][z]
    else     *(float4*)(g_tot + idx) = o;
}

// ---------------------------------------------------------------------------
extern "C" void kernel_launch(void* const* d_in, const int* in_sizes, int n_in,
                              void* d_out, int out_size) {
    const float* xa = (const float*)d_in[0];
    const float* cw = (const float*)d_in[1];
    const int*   vn = (const int*)d_in[2];
    // d_in[3] = cn_idx: structure is repeat(arange(M), dc) -> implicit (e/7)
    const int*   sh = (const int*)d_in[4];

    int iters = in_sizes[1];   // cn_weights length = 8

    k_init<<<BB * (ZZ/32) * 3, dim3(32, 8)>>>(xa);
    k_build_inv<<<1, 256>>>(vn);

    for (int it = 0; it < iters; ++it) {
        k_phase2<<<BB*MC, ZZ>>>(vn, sh, cw, it, it == 0);
        k_phase1<<<BB * (NV/NG), ZZ>>>((it == iters-1) ? (float*)d_out : (float*)nullptr);
    }
}

// round 11
// speedup vs baseline: 1.3595x; 1.1479x over previous
#include <cuda_runtime.h>

// Problem constants (fixed for this registry problem instance)
#define BB 32
#define ZZ 384
#define NV 68
#define MC 46
#define DC 7
#define EE (MC*DC)          // 322
#define NG 4                // variables per phase1 block (68 = 17*4)

// Device scratch (no cudaMalloc allowed)
__device__ float g_tot[BB*NV*ZZ];     // tot_plus = xa + sum(c2v), layout [b][n][z]
__device__ float g_xaT[BB*NV*ZZ];     // transposed xa, layout [b][n][z]
// c2v stored as int8 = 2*value (exact: values are half-integers in [-7.5,7.5]),
// in VARIABLE z-domain: c2v_v[b][e][zv], zv=(zm+shift_e)%Z.
// Phase2 reads/writes at the rotated index zv; phase1 reads un-rotated, packed.
__device__ signed char g_c2v8[BB*EE*ZZ];
__device__ int   g_inv_off[NV+1];     // CSR: variable -> its edges
__device__ int   g_inv_eoff[EE];      // per edge (var-sorted): e*ZZ (byte offset)

// ---------------------------------------------------------------------------
// Init: tiled transpose xa[b][z][n] -> g_xaT/g_tot [b][n][z].
// ---------------------------------------------------------------------------
__global__ void k_init(const float* __restrict__ xa) {
    __shared__ float tile[32][33];
    int bid = blockIdx.x;
    int nt = bid % 3;                 // n-tile (0..2, covers 96 >= 68)
    int zt = (bid / 3) % (ZZ/32);     // z-tile
    int b  = bid / (3 * (ZZ/32));
    int n0 = nt * 32, z0 = zt * 32;
    int tx = threadIdx.x, ty = threadIdx.y;

    int n = n0 + tx;
#pragma unroll
    for (int r = 0; r < 4; r++) {
        int z = z0 + ty + r*8;
        if (n < NV) tile[ty + r*8][tx] = xa[(b*ZZ + z)*NV + n];
    }
    __syncthreads();
#pragma unroll
    for (int r = 0; r < 4; r++) {
        int nn = n0 + ty + r*8;
        int zz = z0 + tx;
        if (nn < NV) {
            float v = tile[tx][ty + r*8];
            int idx = (b*NV + nn)*ZZ + zz;
            g_xaT[idx] = v;
            g_tot[idx] = v;          // iteration 0: c2v = 0 -> tot_plus = xa
        }
    }
}

// ---------------------------------------------------------------------------
// Build inverse index: variable n -> list of e*ZZ.
// ---------------------------------------------------------------------------
__global__ void k_build_inv(const int* __restrict__ vn) {
    __shared__ int off[NV+1];
    __shared__ int cur[NV];
    int t = threadIdx.x;
    for (int i = t; i <= NV; i += blockDim.x) off[i] = 0;
    __syncthreads();
    for (int e = t; e < EE; e += blockDim.x) atomicAdd(&off[vn[e] + 1], 1);
    __syncthreads();
    if (t == 0) {
        int s = 0;
        for (int i = 0; i <= NV; i++) { s += off[i]; off[i] = s; }
    }
    __syncthreads();
    for (int i = t; i <= NV; i += blockDim.x) g_inv_off[i] = off[i];
    for (int i = t; i <  NV; i += blockDim.x) cur[i] = off[i];
    __syncthreads();
    for (int e = t; e < EE; e += blockDim.x) {
        int p = atomicAdd(&cur[vn[e]], 1);
        g_inv_eoff[p] = e * ZZ;
    }
}

// ---------------------------------------------------------------------------
// Phase 2: check-node min-sum. One block per (b, check c), 384 threads = zm.
// Edge j uses rotated index zv_j=(zm+shift_j)%Z for tot read, old-c2v read
// (LDG.S8), and new-c2v write (STG.S8). Byte rows: warp = 32 consecutive
// bytes = 1 sector per edge (4x less L2 traffic than fp32).
// ---------------------------------------------------------------------------
__global__ void __launch_bounds__(ZZ) k_phase2(
    const int* __restrict__ vn, const int* __restrict__ sh,
    const float* __restrict__ cw, int it, int first) {
    int c = blockIdx.x % MC;
    int b = blockIdx.x / MC;
    int zm = threadIdx.x;

    __shared__ int s_n[DC], s_s[DC];
    if (threadIdx.x < DC) {
        int e = c * DC + threadIdx.x;
        s_n[threadIdx.x] = vn[e];
        s_s[threadIdx.x] = sh[e];
    }
    __syncthreads();

    const float* totb = g_tot + b*NV*ZZ;
    signed char* cvb  = g_c2v8 + (b*EE + c*DC)*ZZ;   // edge j row: + j*ZZ
    float w = __ldg(cw + it);

    int zv[DC];
#pragma unroll
    for (int j = 0; j < DC; j++) {
        int t2 = zm + s_s[j]; if (t2 >= ZZ) t2 -= ZZ;
        zv[j] = t2;
    }

    // gather tot + old c2v (independent loads -> MLP)
    float tp[DC];
    int   oldq[DC];
#pragma unroll
    for (int j = 0; j < DC; j++) tp[j]  = totb[s_n[j]*ZZ + zv[j]];
#pragma unroll
    for (int j = 0; j < DC; j++) oldq[j] = first ? 0 : (int)cvb[j*ZZ + zv[j]];

    float mn1 = 1e30f, mn2 = 1e30f;
    int arg = 0;
    unsigned sb = 0;
#pragma unroll
    for (int j = 0; j < DC; j++) {
        float x = tp[j] - (float)oldq[j] * 0.5f;   // exact: oldq/2 half-integer
        x = fminf(fmaxf(x, -20.0f), 20.0f);
        if (x < 0.0f) sb |= (1u << j);
        float a = fabsf(x);
        if (a < mn1) { mn2 = mn1; mn1 = a; arg = j; }
        else         { mn2 = fminf(mn2, a); }
    }
    int par = __popc(sb) & 1;
    // quantize: clip(round(2*w*min), +-15); rintf = round-half-even = jnp.round
    int iq1 = (int)fminf(fmaxf(rintf(2.0f * (w * mn1)), -15.0f), 15.0f);
    int iq2 = (int)fminf(fmaxf(rintf(2.0f * (w * mn2)), -15.0f), 15.0f);

#pragma unroll
    for (int j = 0; j < DC; j++) {
        int q = (j == arg) ? iq2 : iq1;                   // branch-free SEL
        int neg = (par ^ (int)(sb >> j)) & 1;             // extrinsic sign
        cvb[j*ZZ + zv[j]] = (signed char)(neg ? -q : q);
    }
}

// ---------------------------------------------------------------------------
// Phase 1: variable-node sum over int8 c2v, scalar int accumulation.
// One block per (b, group of NG=4 variables), 384 threads.
// Thread -> nn = tid/96 (warp-uniform), handles 4 z's per edge via one LDG.32.
// Sign extension via arithmetic shifts (guaranteed semantics; ptxas emits
// 1 SGXT/BFE per extract). Sums exact ints (|sum| <= 15*deg). Final
// fmaf(sum, 0.5f, xa): sum*0.5 exact (pow2), one rounded add == JAX's
// xa + einsum. Bit-exact. dst==nullptr -> g_tot.
// ---------------------------------------------------------------------------
__global__ void __launch_bounds__(ZZ) k_phase1(float* __restrict__ dst) {
    int n0 = (blockIdx.x % (NV/NG)) * NG;
    int b  = blockIdx.x / (NV/NG);
    int nn = threadIdx.x / (ZZ/4);           // 0..3, uniform per warp
    int z4 = (threadIdx.x % (ZZ/4)) * 4;     // byte (and z) offset of 4 z's
    int n  = n0 + nn;

    __shared__ int s_eo[NG][16];             // deg << 16 always
    __shared__ int s_k0[NG+1];
    if (threadIdx.x <= NG) s_k0[threadIdx.x] = g_inv_off[n0 + threadIdx.x];
    __syncthreads();
    int base = s_k0[0];
    int tot_e = s_k0[NG] - base;
    if (threadIdx.x < tot_e) {
        int eo = g_inv_eoff[base + threadIdx.x];
        int i = threadIdx.x + base;
        int g = 0;
        while (i >= s_k0[g+1]) g++;          // tiny loop, <=4 iters, few threads
        s_eo[g][i - s_k0[g]] = eo;
    }
    __syncthreads();

    int deg = s_k0[nn+1] - s_k0[nn];
    const signed char* cvb = g_c2v8 + b*EE*ZZ + z4;
    int a0 = 0, a1 = 0, a2 = 0, a3 = 0;      // per-z integer accumulators
    for (int k = 0; k < deg; k++) {
        int v = (int)__ldg((const unsigned*)(cvb + s_eo[nn][k]));
        a0 += (v << 24) >> 24;               // sext byte0 (z4+0)
        a1 += (v << 16) >> 24;               // sext byte1 (z4+1)
        a2 += (v <<  8) >> 24;               // sext byte2 (z4+2)
        a3 +=  v        >> 24;               // sext byte3 (z4+3)
    }

    int idx = (b*NV + n)*ZZ + z4;
    float4 xa4 = __ldg((const float4*)(g_xaT + idx));
    float4 o;
    o.x = fmaf((float)a0, 0.5f, xa4.x);      // sum*0.5 exact; one rounded add
    o.y = fmaf((float)a1, 0.5f, xa4.y);
    o.z = fmaf((float)a2, 0.5f, xa4.z);
    o.w = fmaf((float)a3, 0.5f, xa4.w);
    if (dst) *(float4*)(dst + idx)   = o;    // out[b, n*Z + z] == [b][n][z]
    else     *(float4*)(g_tot + idx) = o;
}

// ---------------------------------------------------------------------------
extern "C" void kernel_launch(void* const* d_in, const int* in_sizes, int n_in,
                              void* d_out, int out_size) {
    const float* xa = (const float*)d_in[0];
    const float* cw = (const float*)d_in[1];
    const int*   vn = (const int*)d_in[2];
    // d_in[3] = cn_idx: structure is repeat(arange(M), dc) -> implicit (e/7)
    const int*   sh = (const int*)d_in[4];

    int iters = in_sizes[1];   // cn_weights length = 8

    k_init<<<BB * (ZZ/32) * 3, dim3(32, 8)>>>(xa);
    k_build_inv<<<1, 256>>>(vn);

    for (int it = 0; it < iters; ++it) {
        k_phase2<<<BB*MC, ZZ>>>(vn, sh, cw, it, it == 0);
        k_phase1<<<BB * (NV/NG), ZZ>>>((it == iters-1) ? (float*)d_out : (float*)nullptr);
    }
}